// round 15
// baseline (speedup 1.0000x reference)
#include <cuda_runtime.h>

// MixEHR_Seed: B=64, V=10000, K=64 — GEMM-factorized, 3-launch, v4.
// out: temp_exp_m_batch [64,64], temp_exp_n [V,K], temp_exp_s [V,K], gamma_sr_sum [K], exp_q_z [1]

#define KD      64
#define BD      64
#define VD      10000
#define VCH     16
#define NCH     625           // VD / VCH
#define SEEDBLK 40
#define ETA_F   0.1f
#define BETA_F  0.05f
#define MU_F    0.05f
#define MINI_F  1e-6f

#define OFF_N   4096
#define OFF_S   644096
#define OFF_GSR 1284096
#define OFF_QZ  1284160

// g_colS/ES/EN and g_nseed are zero at module load and re-zeroed by finalize
// each run, so prep can atomicAdd into them without a same-kernel reset race.
__device__ float  g_colS[KD];
__device__ float  g_colES[KD];
__device__ float  g_colEN[KD];
__device__ float2 g_TL[BD * KD];        // (theta, theta*log theta) interleaved
__device__ float  g_P[NCH * BD * KD];   // per-block W@crr partials (10.24 MB)
__device__ float  g_Mseed[BD * KD];
__device__ int    g_nseed;
__device__ int    g_seedlist[VD];
__device__ int    g_flag[VD];

__device__ __forceinline__ float warp_sum(float x) {
    #pragma unroll
    for (int o = 16; o; o >>= 1)
        x += __shfl_xor_sync(0xffffffffu, x, o);
    return x;
}

// ln(x) for positive normal x, FMA-pipe only. |err| ~2e-6.
__device__ __forceinline__ float fast_log(float x) {
    int ix = __float_as_int(x);
    int e  = (ix - 0x3f330000) >> 23;
    float m = __int_as_float(ix - (e << 23));
    float f = m - 1.0f;
    float p = 0.09090909f;
    p = fmaf(p, f, -0.1f);
    p = fmaf(p, f,  0.11111111f);
    p = fmaf(p, f, -0.125f);
    p = fmaf(p, f,  0.14285714f);
    p = fmaf(p, f, -0.16666667f);
    p = fmaf(p, f,  0.2f);
    p = fmaf(p, f, -0.25f);
    p = fmaf(p, f,  0.33333333f);
    p = fmaf(p, f, -0.5f);
    p = fmaf(p, f,  1.0f);
    return fmaf((float)e, 0.69314718f, p * f);
}

// ---- Launch 1: zero + TL + flag/seedlist (warp-aggregated) + float4 colsum ----
// grid 148 x 256 = 37888 threads.
__global__ void prep_kernel(const float* __restrict__ seeds,
                            const float* __restrict__ exp_s,
                            const float* __restrict__ exp_n,
                            const float* __restrict__ exp_m,
                            float* __restrict__ out) {
    const int gid = blockIdx.x * blockDim.x + threadIdx.x;
    const int lane = threadIdx.x & 31;

    if (gid < BD * KD) {
        const float th = exp_m[gid] + ETA_F;
        g_TL[gid] = make_float2(th, th * __logf(th));
        out[gid] = 0.0f;
        g_Mseed[gid] = 0.0f;
    }
    if (gid < KD) out[OFF_GSR + gid] = 0.0f;
    if (gid == 0) out[OFF_QZ] = 0.0f;

    // flag: one thread per row; warp-aggregated seedlist append (few atomics)
    int f = 0;
    if (gid < VD) {
        const float4* sr = reinterpret_cast<const float4*>(seeds + gid * KD);
        #pragma unroll
        for (int q = 0; q < 16; q++) {
            float4 s4 = sr[q];
            f |= (s4.x > 0.0f) | (s4.y > 0.0f) | (s4.z > 0.0f) | (s4.w > 0.0f);
        }
        g_flag[gid] = f;
    }
    const bool w = (gid < VD) && f;
    const unsigned m = __ballot_sync(0xffffffffu, w);
    if (m) {
        const int cnt = __popc(m);
        const int leader = __ffs(m) - 1;
        int base = 0;
        if (lane == leader) base = atomicAdd(&g_nseed, cnt);
        base = __shfl_sync(0xffffffffu, base, leader);
        if (w) g_seedlist[base + __popc(m & ((1u << lane) - 1u))] = gid;
    }

    // colsum: float4 lanes; stride*4 divisible by 64 -> fixed kbase per thread
    {
        const float4* s4 = reinterpret_cast<const float4*>(seeds);
        const float4* e4 = reinterpret_cast<const float4*>(exp_s);
        const float4* n4 = reinterpret_cast<const float4*>(exp_n);
        const int stride4 = gridDim.x * blockDim.x;      // 37888; *4 % 64 == 0
        const int tot4 = VD * KD / 4;                    // 160000
        float a0=0,a1=0,a2=0,a3=0, b0=0,b1=0,b2=0,b3=0, c0=0,c1=0,c2=0,c3=0;
        for (int i = gid; i < tot4; i += stride4) {
            float4 v = s4[i]; a0+=v.x; a1+=v.y; a2+=v.z; a3+=v.w;
            float4 u = e4[i]; b0+=u.x; b1+=u.y; b2+=u.z; b3+=u.w;
            float4 t = n4[i]; c0+=t.x; c1+=t.y; c2+=t.z; c3+=t.w;
        }
        const int kb = (gid * 4) & (KD - 1);
        atomicAdd(&g_colS[kb+0], a0); atomicAdd(&g_colS[kb+1], a1);
        atomicAdd(&g_colS[kb+2], a2); atomicAdd(&g_colS[kb+3], a3);
        atomicAdd(&g_colES[kb+0], b0); atomicAdd(&g_colES[kb+1], b1);
        atomicAdd(&g_colES[kb+2], b2); atomicAdd(&g_colES[kb+3], b3);
        atomicAdd(&g_colEN[kb+0], c0); atomicAdd(&g_colEN[kb+1], c1);
        atomicAdd(&g_colEN[kb+2], c2); atomicAdd(&g_colEN[kb+3], c3);
    }
}

// ---- Launch 2: mega kernel — fused GEMMs (blocks 0..624) + seed rows ----
// fused smem: sCr[16*68] @0 (4352), sCl @4352 (4352), sW[64*17] @8704 (4352),
//             flag @13056 (64), invN @13120 (256), qz @13376 (4)
// seed smem:  sTh64[64*64] = 16384
#define SO_CR   0
#define SO_CL   4352
#define SO_W    8704
#define SO_FLAG 13056
#define SO_INVN 13120
#define SO_QZ   13376
#define SMEM_MEGA 16448

__global__ __launch_bounds__(256, 5) void mega_kernel(
    const float* __restrict__ BOW,
    const float* __restrict__ seeds,
    const float* __restrict__ exp_s,
    const float* __restrict__ exp_n,
    const float* __restrict__ pi,
    float* __restrict__ out)
{
    extern __shared__ char smem[];
    const int tid = threadIdx.x;
    const int lane = tid & 31, warp = tid >> 5;

    if (blockIdx.x < NCH) {
        // ================= FUSED PATH (non-seed rows) =================
        float* sCr   = reinterpret_cast<float*>(smem + SO_CR);
        float* sCl   = reinterpret_cast<float*>(smem + SO_CL);
        float* sW    = reinterpret_cast<float*>(smem + SO_W);
        int*   sFlag = reinterpret_cast<int*>(smem + SO_FLAG);
        float* sInvN = reinterpret_cast<float*>(smem + SO_INVN);
        float* sQz   = reinterpret_cast<float*>(smem + SO_QZ);

        const int v0 = blockIdx.x * VCH;

        if (tid < KD) sInvN[tid] = __fdividef(1.0f, BETA_F * (float)VD + g_colEN[tid]);
        if (tid < VCH) sFlag[tid] = g_flag[v0 + tid];
        if (tid == 0) *sQz = 0.0f;
        __syncthreads();

        // crr / crr*logcrr (v-major, stride 68)
        #pragma unroll
        for (int r = 0; r < 4; r++) {
            const int i = tid + r * 256;        // 0..1023
            const int vl = i >> 6, k = i & 63;
            const float sd = seeds[(v0 + vl) * KD + k];
            const float en = exp_n[(v0 + vl) * KD + k];
            const float c1 = (1.0f - sd) * (BETA_F + en) * sInvN[k];
            sCr[vl * 68 + k] = c1;
            sCl[vl * 68 + k] = c1 * fast_log(c1 + 1e-30f);
        }
        __syncthreads();

        // ---- GEMM1: rp/ab over k; theta planes via L1-resident g_TL LDG ----
        float qz = 0.0f;
        {
            const int tx = tid & 7,  ty = tid >> 3;
            const int vg = tx * 2,   bg = ty * 2;
            float rp00=0,rp01=0,rp10=0,rp11=0;
            float ab00=0,ab01=0,ab10=0,ab11=0;
            const float4* TL4 = reinterpret_cast<const float4*>(g_TL);
            // TL4[(b*64+k)/2] = {th(k), thl(k), th(k+1), thl(k+1)} (k even)
            #pragma unroll 4
            for (int kq = 0; kq < KD; kq += 4) {
                const float4 t0a = TL4[(bg * 64 + kq) >> 1];
                const float4 t0b = TL4[(bg * 64 + kq + 2) >> 1];
                const float4 t1a = TL4[((bg + 1) * 64 + kq) >> 1];
                const float4 t1b = TL4[((bg + 1) * 64 + kq + 2) >> 1];
                const float4 c0 = *reinterpret_cast<const float4*>(&sCr[vg * 68 + kq]);
                const float4 c1 = *reinterpret_cast<const float4*>(&sCr[(vg + 1) * 68 + kq]);
                const float4 d0 = *reinterpret_cast<const float4*>(&sCl[vg * 68 + kq]);
                const float4 d1 = *reinterpret_cast<const float4*>(&sCl[(vg + 1) * 68 + kq]);
                rp00 = fmaf(t0a.x,c0.x,fmaf(t0a.z,c0.y,fmaf(t0b.x,c0.z,fmaf(t0b.z,c0.w,rp00))));
                rp01 = fmaf(t0a.x,c1.x,fmaf(t0a.z,c1.y,fmaf(t0b.x,c1.z,fmaf(t0b.z,c1.w,rp01))));
                rp10 = fmaf(t1a.x,c0.x,fmaf(t1a.z,c0.y,fmaf(t1b.x,c0.z,fmaf(t1b.z,c0.w,rp10))));
                rp11 = fmaf(t1a.x,c1.x,fmaf(t1a.z,c1.y,fmaf(t1b.x,c1.z,fmaf(t1b.z,c1.w,rp11))));
                ab00 = fmaf(t0a.y,c0.x,fmaf(t0a.w,c0.y,fmaf(t0b.y,c0.z,fmaf(t0b.w,c0.w,ab00))));
                ab00 = fmaf(t0a.x,d0.x,fmaf(t0a.z,d0.y,fmaf(t0b.x,d0.z,fmaf(t0b.z,d0.w,ab00))));
                ab01 = fmaf(t0a.y,c1.x,fmaf(t0a.w,c1.y,fmaf(t0b.y,c1.z,fmaf(t0b.w,c1.w,ab01))));
                ab01 = fmaf(t0a.x,d1.x,fmaf(t0a.z,d1.y,fmaf(t0b.x,d1.z,fmaf(t0b.z,d1.w,ab01))));
                ab10 = fmaf(t1a.y,c0.x,fmaf(t1a.w,c0.y,fmaf(t1b.y,c0.z,fmaf(t1b.w,c0.w,ab10))));
                ab10 = fmaf(t1a.x,d0.x,fmaf(t1a.z,d0.y,fmaf(t1b.x,d0.z,fmaf(t1b.z,d0.w,ab10))));
                ab11 = fmaf(t1a.y,c1.x,fmaf(t1a.w,c1.y,fmaf(t1b.y,c1.z,fmaf(t1b.w,c1.w,ab11))));
                ab11 = fmaf(t1a.x,d1.x,fmaf(t1a.z,d1.y,fmaf(t1b.x,d1.z,fmaf(t1b.z,d1.w,ab11))));
            }
            const int f0 = sFlag[vg], f1 = sFlag[vg + 1];
            #pragma unroll
            for (int e = 0; e < 4; e++) {
                const int i = e >> 1, j = e & 1;
                const float r = (e==0)?rp00:(e==1)?rp01:(e==2)?rp10:rp11;
                const float a = (e==0)?ab00:(e==1)?ab01:(e==2)?ab10:ab11;
                const int b = bg + i, vl = vg + j;
                float w = 0.0f;
                if (((j == 0) ? f0 : f1) == 0) {
                    const float cnt = BOW[b * VD + v0 + vl];
                    const float rpm = r + MINI_F;
                    const float inv = __fdividef(1.0f, rpm);
                    w = cnt * inv;
                    if (cnt > 0.0f)
                        qz += a * inv - fast_log(rpm) * (r * inv);
                }
                sW[b * 17 + vl] = w;
            }
        }
        __syncthreads();

        // ---- GEMM2: EN[v,k] = crr * sum_b W[b,v]*theta[b,k]; skip flagged rows ----
        {
            const int vl = tid & 15;
            const int kg = (tid >> 4) * 4;
            const float4* TL4 = reinterpret_cast<const float4*>(g_TL);
            float e0=0,e1=0,e2=0,e3=0;
            #pragma unroll 4
            for (int b = 0; b < BD; b++) {
                const float w = sW[b * 17 + vl];
                const float4 ta = TL4[(b * 64 + kg) >> 1];      // th(kg),thl,th(kg+1),thl
                const float4 tb = TL4[(b * 64 + kg + 2) >> 1];
                e0 = fmaf(w, ta.x, e0); e1 = fmaf(w, ta.z, e1);
                e2 = fmaf(w, tb.x, e2); e3 = fmaf(w, tb.z, e3);
            }
            if (sFlag[vl] == 0) {
                const float4 c4 = *reinterpret_cast<const float4*>(&sCr[vl * 68 + kg]);
                float4 o;
                o.x = e0 * c4.x; o.y = e1 * c4.y; o.z = e2 * c4.z; o.w = e3 * c4.w;
                const int gv = v0 + vl;
                *reinterpret_cast<float4*>(&out[OFF_N + gv * KD + kg]) = o;
                *reinterpret_cast<float4*>(&out[OFF_S + gv * KD + kg]) = make_float4(0.f,0.f,0.f,0.f);
            }
        }

        // ---- GEMM3: P[b,k] = sum_v W[b,v]*crr[v,k] ----
        {
            const int kg  = (tid & 15) * 4;
            const int bg3 = (tid >> 4) * 4;
            float p[4][4] = {};
            #pragma unroll 4
            for (int vl = 0; vl < VCH; vl++) {
                const float4 c4 = *reinterpret_cast<const float4*>(&sCr[vl * 68 + kg]);
                const float w0 = sW[(bg3 + 0) * 17 + vl];
                const float w1 = sW[(bg3 + 1) * 17 + vl];
                const float w2 = sW[(bg3 + 2) * 17 + vl];
                const float w3 = sW[(bg3 + 3) * 17 + vl];
                p[0][0]=fmaf(w0,c4.x,p[0][0]); p[0][1]=fmaf(w0,c4.y,p[0][1]); p[0][2]=fmaf(w0,c4.z,p[0][2]); p[0][3]=fmaf(w0,c4.w,p[0][3]);
                p[1][0]=fmaf(w1,c4.x,p[1][0]); p[1][1]=fmaf(w1,c4.y,p[1][1]); p[1][2]=fmaf(w1,c4.z,p[1][2]); p[1][3]=fmaf(w1,c4.w,p[1][3]);
                p[2][0]=fmaf(w2,c4.x,p[2][0]); p[2][1]=fmaf(w2,c4.y,p[2][1]); p[2][2]=fmaf(w2,c4.z,p[2][2]); p[2][3]=fmaf(w2,c4.w,p[2][3]);
                p[3][0]=fmaf(w3,c4.x,p[3][0]); p[3][1]=fmaf(w3,c4.y,p[3][1]); p[3][2]=fmaf(w3,c4.z,p[3][2]); p[3][3]=fmaf(w3,c4.w,p[3][3]);
            }
            float* dst = g_P + blockIdx.x * (BD * KD);
            #pragma unroll
            for (int i = 0; i < 4; i++)
                *reinterpret_cast<float4*>(&dst[(bg3 + i) * KD + kg]) =
                    make_float4(p[i][0], p[i][1], p[i][2], p[i][3]);
        }

        // qz: warp -> shared -> one global atomic per block
        qz = warp_sum(qz);
        __syncthreads();
        if (lane == 0 && qz != 0.0f) atomicAdd(sQz, qz);
        __syncthreads();
        if (tid == 0 && *sQz != 0.0f) atomicAdd(&out[OFF_QZ], *sQz);

    } else {
        // ================= SEED PATH (one warp per row, exact) =================
        float* sTh64 = reinterpret_cast<float*>(smem);    // [64*64]
        for (int i = tid; i < BD * KD; i += 256) sTh64[i] = g_TL[i].x;
        __syncthreads();

        const int gw = (blockIdx.x - NCH) * 8 + warp;
        const int nwarp = SEEDBLK * 8;
        const int k0 = lane, k1 = lane + 32;
        const float invS0 = __fdividef(1.0f, MU_F * g_colS[k0] + g_colES[k0]);
        const float invS1 = __fdividef(1.0f, MU_F * g_colS[k1] + g_colES[k1]);
        const float invN0 = __fdividef(1.0f, BETA_F * (float)VD + g_colEN[k0]);
        const float invN1 = __fdividef(1.0f, BETA_F * (float)VD + g_colEN[k1]);
        const float pi0 = pi[k0], pi1 = pi[k1];
        const float q0 = 1.0f - pi0, q1 = 1.0f - pi1;
        const int nseed = g_nseed;

        float accGsr0 = 0.0f, accGsr1 = 0.0f, accQz = 0.0f;

        for (int idx = gw; idx < nseed; idx += nwarp) {
            const int v = g_seedlist[idx];
            const int base = v * KD;

            const float sd0 = seeds[base + k0], sd1 = seeds[base + k1];
            const float ps0 = (MU_F  + exp_s[base + k0]) * invS0;
            const float ps1 = (MU_F  + exp_s[base + k1]) * invS1;
            const float pn0 = (BETA_F + exp_n[base + k0]) * invN0;
            const float pn1 = (BETA_F + exp_n[base + k1]) * invN1;
            const float crr0 = (1.0f - sd0) * pn0, crr1 = (1.0f - sd1) * pn1;
            const float css0 = sd0 * ps0 * pi0, css1 = sd1 * ps1 * pi1;
            const float csr0 = sd0 * pn0 * q0,  csr1 = sd1 * pn1 * q1;

            const float cntA = BOW[lane * VD + v];
            const float cntB = BOW[(lane + 32) * VD + v];

            float aN0 = 0.f, aN1 = 0.f, aS0 = 0.f, aS1 = 0.f;

            for (int b = 0; b < BD; b++) {
                const float cnt = __shfl_sync(0xffffffffu, (b < 32) ? cntA : cntB, b & 31);
                if (cnt <= 0.0f) continue;
                const float th0 = sTh64[b * KD + k0];
                const float th1 = sTh64[b * KD + k1];
                float gss0 = th0 * css0, gss1 = th1 * css1;
                float gsr0 = th0 * csr0, gsr1 = th1 * csr1;
                float grr0 = th0 * crr0, grr1 = th1 * crr1;
                float sp = gss0 + gsr0 + gss1 + gsr1;
                float rp = grr0 + grr1;
                #pragma unroll
                for (int o = 16; o; o >>= 1) {
                    sp += __shfl_xor_sync(0xffffffffu, sp, o);
                    rp += __shfl_xor_sync(0xffffffffu, rp, o);
                }
                const float invs = __fdividef(1.0f, sp + MINI_F);
                const float invr = __fdividef(1.0f, rp + MINI_F);
                gss0 *= invs; gss1 *= invs;
                gsr0 *= invs; gsr1 *= invs;
                grr0 *= invr; grr1 *= invr;
                const float gam0 = pi0 * gss0 + q0 * (gsr0 + grr0);
                const float gam1 = pi1 * gss1 + q1 * (gsr1 + grr1);
                aN0 += (gsr0 + grr0) * cnt; aN1 += (gsr1 + grr1) * cnt;
                aS0 += gss0 * cnt;          aS1 += gss1 * cnt;
                accGsr0 += gsr0;            accGsr1 += gsr1;
                accQz += gam0 * __logf(gam0 + MINI_F) + gam1 * __logf(gam1 + MINI_F);
                atomicAdd(&g_Mseed[b * KD + k0], gam0 * cnt);
                atomicAdd(&g_Mseed[b * KD + k1], gam1 * cnt);
            }
            out[OFF_N + base + k0] = aN0; out[OFF_N + base + k1] = aN1;
            out[OFF_S + base + k0] = aS0; out[OFF_S + base + k1] = aS1;
        }

        if (accGsr0 != 0.0f) atomicAdd(&out[OFF_GSR + k0], accGsr0);
        if (accGsr1 != 0.0f) atomicAdd(&out[OFF_GSR + k1], accGsr1);
        accQz = warp_sum(accQz);
        if (lane == 0 && accQz != 0.0f) atomicAdd(&out[OFF_QZ], accQz);
    }
}

// ---- Launch 3: finalize exp_m; reset persistent accumulators for next run ----
__global__ void finalize_kernel(float* __restrict__ out) {
    const int i = blockIdx.x * blockDim.x + threadIdx.x;   // 0..4095
    const int j0 = blockIdx.y * 25;
    float s = 0.0f;
    #pragma unroll 5
    for (int j = 0; j < 25; j++)
        s += g_P[(j0 + j) * (BD * KD) + i];
    float add = g_TL[i].x * s;
    if (blockIdx.y == 0) add += g_Mseed[i];
    atomicAdd(&out[i], add);
    if (blockIdx.y == 0) {
        if (i < KD) { g_colS[i] = 0.0f; g_colES[i] = 0.0f; g_colEN[i] = 0.0f; }
        if (i == 0) g_nseed = 0;
    }
}

extern "C" void kernel_launch(void* const* d_in, const int* in_sizes, int n_in,
                              void* d_out, int out_size) {
    const float* BOW   = (const float*)d_in[0];
    const float* seeds = (const float*)d_in[1];
    const float* exp_m = (const float*)d_in[2];
    const float* exp_s = (const float*)d_in[3];
    const float* exp_n = (const float*)d_in[4];
    const float* pi    = (const float*)d_in[5];
    float* out = (float*)d_out;

    prep_kernel<<<148, 256>>>(seeds, exp_s, exp_n, exp_m, out);
    mega_kernel<<<NCH + SEEDBLK, 256, SMEM_MEGA>>>(BOW, seeds, exp_s, exp_n, pi, out);
    finalize_kernel<<<dim3(16, 25), 256>>>(out);
}

// round 16
// speedup vs baseline: 2.1915x; 2.1915x over previous
#include <cuda_runtime.h>

// MixEHR_Seed: B=64, V=10000, K=64 — R7 champion structure, 3 launches.
// out: temp_exp_m_batch [64,64], temp_exp_n [V,K], temp_exp_s [V,K], gamma_sr_sum [K], exp_q_z [1]

#define KD    64
#define BD    64
#define VD    10000
#define TQ    4                 // v per tile
#define NTILE (VD / TQ)         // 2500
#define NBLK  444               // 3 CTAs x 148 SMs
#define NSLICE 32               // exp_m scratch slices
#define ETA_F  0.1f
#define BETA_F 0.05f
#define MU_F   0.05f
#define MINI_F 1e-6f

#define OFF_N   4096
#define OFF_S   644096
#define OFF_GSR 1284096
#define OFF_QZ  1284160

// Zero at module load; re-zeroed by reduce_m each run (reset-for-next-replay).
__device__ float g_colS[KD];
__device__ float g_colES[KD];
__device__ float g_colEN[KD];
__device__ float g_scratch32[NSLICE * BD * KD];   // 512 KB

__device__ __forceinline__ float warp_sum(float x) {
    #pragma unroll
    for (int o = 16; o; o >>= 1)
        x += __shfl_xor_sync(0xffffffffu, x, o);
    return x;
}

// ---- Launch 1: column sums + zero the small output regions ----
// g_colS/ES/EN are zero on entry (module load or previous run's reduce_m).
__global__ void colsum_kernel(const float* __restrict__ seeds,
                              const float* __restrict__ exp_s,
                              const float* __restrict__ exp_n,
                              float* __restrict__ out) {
    const int tid = blockIdx.x * blockDim.x + threadIdx.x;
    if (tid < BD * KD) out[tid] = 0.0f;              // temp_exp_m_batch (reduce adds)
    if (tid < KD) out[OFF_GSR + tid] = 0.0f;         // gamma_sr_sum
    if (tid == 0) out[OFF_QZ] = 0.0f;                // exp_q_z

    const int stride = gridDim.x * blockDim.x;
    float a = 0.0f, b = 0.0f, c = 0.0f;
    for (int i = tid; i < VD * KD; i += stride) {
        a += seeds[i]; b += exp_s[i]; c += exp_n[i];
    }
    const int k = tid & (KD - 1);
    atomicAdd(&g_colS[k], a);
    atomicAdd(&g_colES[k], b);
    atomicAdd(&g_colEN[k], c);
}

// ---- Launch 2: main kernel (identical to the 55.3us champion) ----
__global__ __launch_bounds__(256, 3) void main_kernel(
    const float* __restrict__ BOW,
    const float* __restrict__ seeds,
    const float* __restrict__ exp_m,
    const float* __restrict__ exp_s,
    const float* __restrict__ exp_n,
    const float* __restrict__ pi,
    float* __restrict__ out)
{
    __shared__ float2 sh_thlt[BD * KD];     // {theta, log(theta)}  32 KB
    __shared__ float  sh_pN[8][TQ * KD];    // aN partials per warp  8 KB
    __shared__ float  sh_pS[8][TQ * KD];    // aS partials per warp  8 KB
    __shared__ float  sh_gsr[KD];
    __shared__ float  sh_qz;

    for (int i = threadIdx.x; i < BD * KD; i += blockDim.x) {
        float th = exp_m[i] + ETA_F;
        sh_thlt[i] = make_float2(th, __logf(th));
    }
    if (threadIdx.x < KD) sh_gsr[threadIdx.x] = 0.0f;
    if (threadIdx.x == 0) sh_qz = 0.0f;
    __syncthreads();

    const int lane = threadIdx.x & 31;
    const int warp = threadIdx.x >> 5;
    const int k0 = lane, k1 = lane + 32;
    const int b0 = warp * 8;                // this warp owns b in [b0, b0+8)

    const float invS0 = 1.0f / (MU_F * g_colS[k0] + g_colES[k0]);
    const float invS1 = 1.0f / (MU_F * g_colS[k1] + g_colES[k1]);
    const float invN0 = 1.0f / (BETA_F * (float)VD + g_colEN[k0]);
    const float invN1 = 1.0f / (BETA_F * (float)VD + g_colEN[k1]);
    const float pi0 = pi[k0], pi1 = pi[k1];
    const float q0 = 1.0f - pi0, q1 = 1.0f - pi1;

    float accM0[8], accM1[8];
    #pragma unroll
    for (int j = 0; j < 8; j++) { accM0[j] = 0.0f; accM1[j] = 0.0f; }
    float accGsr0 = 0.0f, accGsr1 = 0.0f, accQz = 0.0f;

    for (int tile = blockIdx.x; tile < NTILE; tile += gridDim.x) {
        const int v0 = tile * TQ;

        // per-row constants
        float crr0[TQ], crr1[TQ], lc0[TQ], lc1[TQ];
        bool rowseed[TQ];
        bool tileseed = false;
        #pragma unroll
        for (int t = 0; t < TQ; t++) {
            const int base = (v0 + t) * KD;
            const float sd0 = seeds[base + k0], sd1 = seeds[base + k1];
            const float pn0 = (BETA_F + exp_n[base + k0]) * invN0;
            const float pn1 = (BETA_F + exp_n[base + k1]) * invN1;
            crr0[t] = (1.0f - sd0) * pn0;
            crr1[t] = (1.0f - sd1) * pn1;
            rowseed[t] = __ballot_sync(0xffffffffu, (sd0 > 0.0f) || (sd1 > 0.0f)) != 0u;
            tileseed |= rowseed[t];
            lc0[t] = __logf(crr0[t] + 1e-30f);
            lc1[t] = __logf(crr1[t] + 1e-30f);
        }

        float aN0[TQ], aN1[TQ], aS0[TQ], aS1[TQ];
        #pragma unroll
        for (int t = 0; t < TQ; t++) { aN0[t]=0.f; aN1[t]=0.f; aS0[t]=0.f; aS1[t]=0.f; }

        if (!tileseed) {
            // ---------------- FAST PATH ----------------
            #pragma unroll
            for (int j = 0; j < 8; j++) {
                const int b = b0 + j;
                const float4 c4 = *reinterpret_cast<const float4*>(BOW + b * VD + v0);
                const float cntv[TQ] = {c4.x, c4.y, c4.z, c4.w};
                const float2 tl0 = sh_thlt[b * KD + k0];
                const float2 tl1 = sh_thlt[b * KD + k1];

                float grr0v[TQ], grr1v[TQ], rpv[TQ];
                #pragma unroll
                for (int t = 0; t < TQ; t++) {
                    grr0v[t] = tl0.x * crr0[t];
                    grr1v[t] = tl1.x * crr1[t];
                    rpv[t] = grr0v[t] + grr1v[t];
                }
                // 4 independent butterflies (ILP covers SHFL latency)
                #pragma unroll
                for (int o = 16; o; o >>= 1) {
                    #pragma unroll
                    for (int t = 0; t < TQ; t++)
                        rpv[t] += __shfl_xor_sync(0xffffffffu, rpv[t], o);
                }
                #pragma unroll
                for (int t = 0; t < TQ; t++) {
                    const float rpm = rpv[t] + MINI_F;
                    const float inv = __fdividef(1.0f, rpm);
                    const float lrp = __logf(rpm);
                    const float g0 = grr0v[t] * inv;
                    const float g1 = grr1v[t] * inv;
                    const float cnt = cntv[t];
                    const float p0 = g0 * cnt, p1 = g1 * cnt;
                    aN0[t] += p0; aN1[t] += p1;
                    accM0[j] += p0; accM1[j] += p1;
                    const float m = (cnt > 0.0f) ? 1.0f : 0.0f;
                    const float e = g0 * ((tl0.y + lc0[t]) - lrp)
                                  + g1 * ((tl1.y + lc1[t]) - lrp);
                    accQz = fmaf(m, e, accQz);
                }
            }
        } else {
            // ---------------- SEED-TILE PATH ----------------
            #pragma unroll
            for (int j = 0; j < 8; j++) {
                const int b = b0 + j;
                const float4 c4 = *reinterpret_cast<const float4*>(BOW + b * VD + v0);
                const float cntv[TQ] = {c4.x, c4.y, c4.z, c4.w};
                const float2 tl0 = sh_thlt[b * KD + k0];
                const float2 tl1 = sh_thlt[b * KD + k1];

                #pragma unroll
                for (int t = 0; t < TQ; t++) {
                    const float cnt = cntv[t];
                    const float m = (cnt > 0.0f) ? 1.0f : 0.0f;
                    if (rowseed[t]) {
                        const int base = (v0 + t) * KD;
                        const float sd0 = seeds[base + k0], sd1 = seeds[base + k1];
                        const float ps0 = (MU_F  + exp_s[base + k0]) * invS0;
                        const float ps1 = (MU_F  + exp_s[base + k1]) * invS1;
                        const float pn0 = (BETA_F + exp_n[base + k0]) * invN0;
                        const float pn1 = (BETA_F + exp_n[base + k1]) * invN1;
                        float gss0 = tl0.x * sd0 * ps0 * pi0;
                        float gss1 = tl1.x * sd1 * ps1 * pi1;
                        float gsr0 = tl0.x * sd0 * pn0 * q0;
                        float gsr1 = tl1.x * sd1 * pn1 * q1;
                        float grr0 = tl0.x * crr0[t];
                        float grr1 = tl1.x * crr1[t];
                        float sp = gss0 + gsr0 + gss1 + gsr1;
                        float rp = grr0 + grr1;
                        #pragma unroll
                        for (int o = 16; o; o >>= 1) {
                            sp += __shfl_xor_sync(0xffffffffu, sp, o);
                            rp += __shfl_xor_sync(0xffffffffu, rp, o);
                        }
                        const float invs = __fdividef(1.0f, sp + MINI_F);
                        const float invr = __fdividef(1.0f, rp + MINI_F);
                        gss0 *= invs; gss1 *= invs;
                        gsr0 *= invs; gsr1 *= invs;
                        grr0 *= invr; grr1 *= invr;
                        const float gam0 = pi0 * gss0 + q0 * (gsr0 + grr0);
                        const float gam1 = pi1 * gss1 + q1 * (gsr1 + grr1);
                        accM0[j] += gam0 * cnt; accM1[j] += gam1 * cnt;
                        aN0[t] += (gsr0 + grr0) * cnt; aN1[t] += (gsr1 + grr1) * cnt;
                        aS0[t] += gss0 * cnt;          aS1[t] += gss1 * cnt;
                        accGsr0 += m * gsr0;           accGsr1 += m * gsr1;
                        accQz += m * (gam0 * __logf(gam0 + MINI_F)
                                    + gam1 * __logf(gam1 + MINI_F));
                    } else {
                        float grr0 = tl0.x * crr0[t];
                        float grr1 = tl1.x * crr1[t];
                        const float rpm = warp_sum(grr0 + grr1) + MINI_F;
                        const float inv = __fdividef(1.0f, rpm);
                        const float lrp = __logf(rpm);
                        const float g0 = grr0 * inv, g1 = grr1 * inv;
                        const float p0 = g0 * cnt, p1 = g1 * cnt;
                        aN0[t] += p0; aN1[t] += p1;
                        accM0[j] += p0; accM1[j] += p1;
                        const float e = g0 * ((tl0.y + lc0[t]) - lrp)
                                      + g1 * ((tl1.y + lc1[t]) - lrp);
                        accQz = fmaf(m, e, accQz);
                    }
                }
            }
        }

        // write per-warp partials, cross-warp reduce, store temp_exp_n / temp_exp_s
        #pragma unroll
        for (int t = 0; t < TQ; t++) {
            sh_pN[warp][t * KD + k0] = aN0[t];
            sh_pN[warp][t * KD + k1] = aN1[t];
            sh_pS[warp][t * KD + k0] = aS0[t];
            sh_pS[warp][t * KD + k1] = aS1[t];
        }
        __syncthreads();
        {
            const int tid = threadIdx.x;   // tid = t*64 + k
            float sN = 0.0f;
            #pragma unroll
            for (int w = 0; w < 8; w++) sN += sh_pN[w][tid];
            out[OFF_N + v0 * KD + tid] = sN;
            float sS = 0.0f;
            if (tileseed) {
                #pragma unroll
                for (int w = 0; w < 8; w++) sS += sh_pS[w][tid];
            }
            out[OFF_S + v0 * KD + tid] = sS;
        }
        __syncthreads();
    }

    // epilogue: exp_m register partials -> 32-slice scratch via spread atomics
    {
        float* dst = g_scratch32 + (blockIdx.x & (NSLICE - 1)) * (BD * KD);
        #pragma unroll
        for (int j = 0; j < 8; j++) {
            atomicAdd(&dst[(b0 + j) * KD + k0], accM0[j]);
            atomicAdd(&dst[(b0 + j) * KD + k1], accM1[j]);
        }
    }
    atomicAdd(&sh_gsr[k0], accGsr0);
    atomicAdd(&sh_gsr[k1], accGsr1);
    const float qzw = warp_sum(accQz);
    if (lane == 0) atomicAdd(&sh_qz, qzw);
    __syncthreads();
    if (threadIdx.x < KD) atomicAdd(&out[OFF_GSR + threadIdx.x], sh_gsr[threadIdx.x]);
    if (threadIdx.x == 0) atomicAdd(&out[OFF_QZ], sh_qz);
}

// ---- Launch 3: reduce scratch32 -> out[0..4095]; reset accumulators for next run ----
// grid (16,8): y-chunk of 4 slices. Each thread re-zeros the entries it read.
__global__ void reduce_m_kernel(float* __restrict__ out) {
    const int i = blockIdx.x * blockDim.x + threadIdx.x;   // 0..4095
    const int j0 = blockIdx.y * 4;
    float s = 0.0f;
    #pragma unroll
    for (int j = 0; j < 4; j++) {
        const int idx = (j0 + j) * (BD * KD) + i;
        s += g_scratch32[idx];
        g_scratch32[idx] = 0.0f;                           // reset for next replay
    }
    atomicAdd(&out[i], s);
    if (blockIdx.y == 0 && i < KD) {                       // reset colsums too
        g_colS[i] = 0.0f; g_colES[i] = 0.0f; g_colEN[i] = 0.0f;
    }
}

extern "C" void kernel_launch(void* const* d_in, const int* in_sizes, int n_in,
                              void* d_out, int out_size) {
    const float* BOW   = (const float*)d_in[0];
    const float* seeds = (const float*)d_in[1];
    const float* exp_m = (const float*)d_in[2];
    const float* exp_s = (const float*)d_in[3];
    const float* exp_n = (const float*)d_in[4];
    const float* pi    = (const float*)d_in[5];
    float* out = (float*)d_out;

    colsum_kernel<<<592, 256>>>(seeds, exp_s, exp_n, out);
    main_kernel<<<NBLK, 256>>>(BOW, seeds, exp_m, exp_s, exp_n, pi, out);
    reduce_m_kernel<<<dim3(16, 8), 256>>>(out);
}

// round 17
// speedup vs baseline: 2.5662x; 1.1710x over previous
#include <cuda_runtime.h>

// MixEHR_Seed: B=64, V=10000, K=64 — champion main + latency-optimal aux kernels.
// out: temp_exp_m_batch [64,64], temp_exp_n [V,K], temp_exp_s [V,K], gamma_sr_sum [K], exp_q_z [1]

#define KD    64
#define BD    64
#define VD    10000
#define TQ    4                 // v per tile
#define NTILE (VD / TQ)         // 2500
#define NBLK  444               // 3 CTAs x 148 SMs
#define NSLICE 32               // exp_m scratch slices
#define ETA_F  0.1f
#define BETA_F 0.05f
#define MU_F   0.05f
#define MINI_F 1e-6f

#define OFF_N   4096
#define OFF_S   644096
#define OFF_GSR 1284096
#define OFF_QZ  1284160

// Zero at module load; re-zeroed by reduce_m each run (reset-for-next-replay).
__device__ float g_colS[KD];
__device__ float g_colES[KD];
__device__ float g_colEN[KD];
__device__ float g_scratch32[NSLICE * BD * KD];   // 512 KB

__device__ __forceinline__ float warp_sum(float x) {
    #pragma unroll
    for (int o = 16; o; o >>= 1)
        x += __shfl_xor_sync(0xffffffffu, x, o);
    return x;
}

// ---- Launch 1: column sums (1 float4/thread/array) + zero small output regions ----
// grid 625 x 256 = 160000 threads = VD*KD/4 float4 lanes exactly.
__global__ void colsum_kernel(const float* __restrict__ seeds,
                              const float* __restrict__ exp_s,
                              const float* __restrict__ exp_n,
                              float* __restrict__ out) {
    __shared__ float sS[KD], sES[KD], sEN[KD];
    const int tid = threadIdx.x;
    const int lane = tid & 31;
    const int gid = blockIdx.x * 256 + tid;

    if (tid < KD) { sS[tid] = 0.0f; sES[tid] = 0.0f; sEN[tid] = 0.0f; }

    // zero output head regions (first blocks)
    if (gid < BD * KD) out[gid] = 0.0f;
    if (gid < KD) out[OFF_GSR + gid] = 0.0f;
    if (gid == 0) out[OFF_QZ] = 0.0f;
    __syncthreads();

    // one float4 from each array; k-base fixed per thread
    float4 a = reinterpret_cast<const float4*>(seeds)[gid];
    float4 b = reinterpret_cast<const float4*>(exp_s)[gid];
    float4 c = reinterpret_cast<const float4*>(exp_n)[gid];

    // lane L and L+16 have the same k-base ((gid*4) mod 64 has period 16)
    a.x += __shfl_down_sync(0xffffffffu, a.x, 16);
    a.y += __shfl_down_sync(0xffffffffu, a.y, 16);
    a.z += __shfl_down_sync(0xffffffffu, a.z, 16);
    a.w += __shfl_down_sync(0xffffffffu, a.w, 16);
    b.x += __shfl_down_sync(0xffffffffu, b.x, 16);
    b.y += __shfl_down_sync(0xffffffffu, b.y, 16);
    b.z += __shfl_down_sync(0xffffffffu, b.z, 16);
    b.w += __shfl_down_sync(0xffffffffu, b.w, 16);
    c.x += __shfl_down_sync(0xffffffffu, c.x, 16);
    c.y += __shfl_down_sync(0xffffffffu, c.y, 16);
    c.z += __shfl_down_sync(0xffffffffu, c.z, 16);
    c.w += __shfl_down_sync(0xffffffffu, c.w, 16);

    if (lane < 16) {
        const int kb = (gid * 4) & (KD - 1);
        atomicAdd(&sS[kb + 0], a.x);  atomicAdd(&sS[kb + 1], a.y);
        atomicAdd(&sS[kb + 2], a.z);  atomicAdd(&sS[kb + 3], a.w);
        atomicAdd(&sES[kb + 0], b.x); atomicAdd(&sES[kb + 1], b.y);
        atomicAdd(&sES[kb + 2], b.z); atomicAdd(&sES[kb + 3], b.w);
        atomicAdd(&sEN[kb + 0], c.x); atomicAdd(&sEN[kb + 1], c.y);
        atomicAdd(&sEN[kb + 2], c.z); atomicAdd(&sEN[kb + 3], c.w);
    }
    __syncthreads();
    if (tid < KD) {
        atomicAdd(&g_colS[tid], sS[tid]);
        atomicAdd(&g_colES[tid], sES[tid]);
        atomicAdd(&g_colEN[tid], sEN[tid]);
    }
}

// ---- Launch 2: main kernel (identical to the 55.3us champion) ----
__global__ __launch_bounds__(256, 3) void main_kernel(
    const float* __restrict__ BOW,
    const float* __restrict__ seeds,
    const float* __restrict__ exp_m,
    const float* __restrict__ exp_s,
    const float* __restrict__ exp_n,
    const float* __restrict__ pi,
    float* __restrict__ out)
{
    __shared__ float2 sh_thlt[BD * KD];     // {theta, log(theta)}  32 KB
    __shared__ float  sh_pN[8][TQ * KD];    // aN partials per warp  8 KB
    __shared__ float  sh_pS[8][TQ * KD];    // aS partials per warp  8 KB
    __shared__ float  sh_gsr[KD];
    __shared__ float  sh_qz;

    for (int i = threadIdx.x; i < BD * KD; i += blockDim.x) {
        float th = exp_m[i] + ETA_F;
        sh_thlt[i] = make_float2(th, __logf(th));
    }
    if (threadIdx.x < KD) sh_gsr[threadIdx.x] = 0.0f;
    if (threadIdx.x == 0) sh_qz = 0.0f;
    __syncthreads();

    const int lane = threadIdx.x & 31;
    const int warp = threadIdx.x >> 5;
    const int k0 = lane, k1 = lane + 32;
    const int b0 = warp * 8;                // this warp owns b in [b0, b0+8)

    const float invS0 = 1.0f / (MU_F * g_colS[k0] + g_colES[k0]);
    const float invS1 = 1.0f / (MU_F * g_colS[k1] + g_colES[k1]);
    const float invN0 = 1.0f / (BETA_F * (float)VD + g_colEN[k0]);
    const float invN1 = 1.0f / (BETA_F * (float)VD + g_colEN[k1]);
    const float pi0 = pi[k0], pi1 = pi[k1];
    const float q0 = 1.0f - pi0, q1 = 1.0f - pi1;

    float accM0[8], accM1[8];
    #pragma unroll
    for (int j = 0; j < 8; j++) { accM0[j] = 0.0f; accM1[j] = 0.0f; }
    float accGsr0 = 0.0f, accGsr1 = 0.0f, accQz = 0.0f;

    for (int tile = blockIdx.x; tile < NTILE; tile += gridDim.x) {
        const int v0 = tile * TQ;

        // per-row constants
        float crr0[TQ], crr1[TQ], lc0[TQ], lc1[TQ];
        bool rowseed[TQ];
        bool tileseed = false;
        #pragma unroll
        for (int t = 0; t < TQ; t++) {
            const int base = (v0 + t) * KD;
            const float sd0 = seeds[base + k0], sd1 = seeds[base + k1];
            const float pn0 = (BETA_F + exp_n[base + k0]) * invN0;
            const float pn1 = (BETA_F + exp_n[base + k1]) * invN1;
            crr0[t] = (1.0f - sd0) * pn0;
            crr1[t] = (1.0f - sd1) * pn1;
            rowseed[t] = __ballot_sync(0xffffffffu, (sd0 > 0.0f) || (sd1 > 0.0f)) != 0u;
            tileseed |= rowseed[t];
            lc0[t] = __logf(crr0[t] + 1e-30f);
            lc1[t] = __logf(crr1[t] + 1e-30f);
        }

        float aN0[TQ], aN1[TQ], aS0[TQ], aS1[TQ];
        #pragma unroll
        for (int t = 0; t < TQ; t++) { aN0[t]=0.f; aN1[t]=0.f; aS0[t]=0.f; aS1[t]=0.f; }

        if (!tileseed) {
            // ---------------- FAST PATH ----------------
            #pragma unroll
            for (int j = 0; j < 8; j++) {
                const int b = b0 + j;
                const float4 c4 = *reinterpret_cast<const float4*>(BOW + b * VD + v0);
                const float cntv[TQ] = {c4.x, c4.y, c4.z, c4.w};
                const float2 tl0 = sh_thlt[b * KD + k0];
                const float2 tl1 = sh_thlt[b * KD + k1];

                float grr0v[TQ], grr1v[TQ], rpv[TQ];
                #pragma unroll
                for (int t = 0; t < TQ; t++) {
                    grr0v[t] = tl0.x * crr0[t];
                    grr1v[t] = tl1.x * crr1[t];
                    rpv[t] = grr0v[t] + grr1v[t];
                }
                // 4 independent butterflies (ILP covers SHFL latency)
                #pragma unroll
                for (int o = 16; o; o >>= 1) {
                    #pragma unroll
                    for (int t = 0; t < TQ; t++)
                        rpv[t] += __shfl_xor_sync(0xffffffffu, rpv[t], o);
                }
                #pragma unroll
                for (int t = 0; t < TQ; t++) {
                    const float rpm = rpv[t] + MINI_F;
                    const float inv = __fdividef(1.0f, rpm);
                    const float lrp = __logf(rpm);
                    const float g0 = grr0v[t] * inv;
                    const float g1 = grr1v[t] * inv;
                    const float cnt = cntv[t];
                    const float p0 = g0 * cnt, p1 = g1 * cnt;
                    aN0[t] += p0; aN1[t] += p1;
                    accM0[j] += p0; accM1[j] += p1;
                    const float m = (cnt > 0.0f) ? 1.0f : 0.0f;
                    const float e = g0 * ((tl0.y + lc0[t]) - lrp)
                                  + g1 * ((tl1.y + lc1[t]) - lrp);
                    accQz = fmaf(m, e, accQz);
                }
            }
        } else {
            // ---------------- SEED-TILE PATH ----------------
            #pragma unroll
            for (int j = 0; j < 8; j++) {
                const int b = b0 + j;
                const float4 c4 = *reinterpret_cast<const float4*>(BOW + b * VD + v0);
                const float cntv[TQ] = {c4.x, c4.y, c4.z, c4.w};
                const float2 tl0 = sh_thlt[b * KD + k0];
                const float2 tl1 = sh_thlt[b * KD + k1];

                #pragma unroll
                for (int t = 0; t < TQ; t++) {
                    const float cnt = cntv[t];
                    const float m = (cnt > 0.0f) ? 1.0f : 0.0f;
                    if (rowseed[t]) {
                        const int base = (v0 + t) * KD;
                        const float sd0 = seeds[base + k0], sd1 = seeds[base + k1];
                        const float ps0 = (MU_F  + exp_s[base + k0]) * invS0;
                        const float ps1 = (MU_F  + exp_s[base + k1]) * invS1;
                        const float pn0 = (BETA_F + exp_n[base + k0]) * invN0;
                        const float pn1 = (BETA_F + exp_n[base + k1]) * invN1;
                        float gss0 = tl0.x * sd0 * ps0 * pi0;
                        float gss1 = tl1.x * sd1 * ps1 * pi1;
                        float gsr0 = tl0.x * sd0 * pn0 * q0;
                        float gsr1 = tl1.x * sd1 * pn1 * q1;
                        float grr0 = tl0.x * crr0[t];
                        float grr1 = tl1.x * crr1[t];
                        float sp = gss0 + gsr0 + gss1 + gsr1;
                        float rp = grr0 + grr1;
                        #pragma unroll
                        for (int o = 16; o; o >>= 1) {
                            sp += __shfl_xor_sync(0xffffffffu, sp, o);
                            rp += __shfl_xor_sync(0xffffffffu, rp, o);
                        }
                        const float invs = __fdividef(1.0f, sp + MINI_F);
                        const float invr = __fdividef(1.0f, rp + MINI_F);
                        gss0 *= invs; gss1 *= invs;
                        gsr0 *= invs; gsr1 *= invs;
                        grr0 *= invr; grr1 *= invr;
                        const float gam0 = pi0 * gss0 + q0 * (gsr0 + grr0);
                        const float gam1 = pi1 * gss1 + q1 * (gsr1 + grr1);
                        accM0[j] += gam0 * cnt; accM1[j] += gam1 * cnt;
                        aN0[t] += (gsr0 + grr0) * cnt; aN1[t] += (gsr1 + grr1) * cnt;
                        aS0[t] += gss0 * cnt;          aS1[t] += gss1 * cnt;
                        accGsr0 += m * gsr0;           accGsr1 += m * gsr1;
                        accQz += m * (gam0 * __logf(gam0 + MINI_F)
                                    + gam1 * __logf(gam1 + MINI_F));
                    } else {
                        float grr0 = tl0.x * crr0[t];
                        float grr1 = tl1.x * crr1[t];
                        const float rpm = warp_sum(grr0 + grr1) + MINI_F;
                        const float inv = __fdividef(1.0f, rpm);
                        const float lrp = __logf(rpm);
                        const float g0 = grr0 * inv, g1 = grr1 * inv;
                        const float p0 = g0 * cnt, p1 = g1 * cnt;
                        aN0[t] += p0; aN1[t] += p1;
                        accM0[j] += p0; accM1[j] += p1;
                        const float e = g0 * ((tl0.y + lc0[t]) - lrp)
                                      + g1 * ((tl1.y + lc1[t]) - lrp);
                        accQz = fmaf(m, e, accQz);
                    }
                }
            }
        }

        // write per-warp partials, cross-warp reduce, store temp_exp_n / temp_exp_s
        #pragma unroll
        for (int t = 0; t < TQ; t++) {
            sh_pN[warp][t * KD + k0] = aN0[t];
            sh_pN[warp][t * KD + k1] = aN1[t];
            sh_pS[warp][t * KD + k0] = aS0[t];
            sh_pS[warp][t * KD + k1] = aS1[t];
        }
        __syncthreads();
        {
            const int tid = threadIdx.x;   // tid = t*64 + k
            float sN = 0.0f;
            #pragma unroll
            for (int w = 0; w < 8; w++) sN += sh_pN[w][tid];
            out[OFF_N + v0 * KD + tid] = sN;
            float sS = 0.0f;
            if (tileseed) {
                #pragma unroll
                for (int w = 0; w < 8; w++) sS += sh_pS[w][tid];
            }
            out[OFF_S + v0 * KD + tid] = sS;
        }
        __syncthreads();
    }

    // epilogue: exp_m register partials -> 32-slice scratch via spread atomics
    {
        float* dst = g_scratch32 + (blockIdx.x & (NSLICE - 1)) * (BD * KD);
        #pragma unroll
        for (int j = 0; j < 8; j++) {
            atomicAdd(&dst[(b0 + j) * KD + k0], accM0[j]);
            atomicAdd(&dst[(b0 + j) * KD + k1], accM1[j]);
        }
    }
    atomicAdd(&sh_gsr[k0], accGsr0);
    atomicAdd(&sh_gsr[k1], accGsr1);
    const float qzw = warp_sum(accQz);
    if (lane == 0) atomicAdd(&sh_qz, qzw);
    __syncthreads();
    if (threadIdx.x < KD) atomicAdd(&out[OFF_GSR + threadIdx.x], sh_gsr[threadIdx.x]);
    if (threadIdx.x == 0) atomicAdd(&out[OFF_QZ], sh_qz);
}

// ---- Launch 3: reduce scratch32 -> out[0..4095], 1 element/thread; reset state ----
// grid (16, 32) x 256 = 131072 threads = NSLICE*BD*KD exactly.
__global__ void reduce_m_kernel(float* __restrict__ out) {
    const int i = blockIdx.x * blockDim.x + threadIdx.x;   // 0..4095
    const int j = blockIdx.y;                              // slice 0..31
    const int idx = j * (BD * KD) + i;
    const float v = g_scratch32[idx];
    g_scratch32[idx] = 0.0f;                               // reset for next replay
    atomicAdd(&out[i], v);                                 // 32 writers per address
    if (j == 0 && i < KD) {                                // reset colsums too
        g_colS[i] = 0.0f; g_colES[i] = 0.0f; g_colEN[i] = 0.0f;
    }
}

extern "C" void kernel_launch(void* const* d_in, const int* in_sizes, int n_in,
                              void* d_out, int out_size) {
    const float* BOW   = (const float*)d_in[0];
    const float* seeds = (const float*)d_in[1];
    const float* exp_m = (const float*)d_in[2];
    const float* exp_s = (const float*)d_in[3];
    const float* exp_n = (const float*)d_in[4];
    const float* pi    = (const float*)d_in[5];
    float* out = (float*)d_out;

    colsum_kernel<<<625, 256>>>(seeds, exp_s, exp_n, out);
    main_kernel<<<NBLK, 256>>>(BOW, seeds, exp_m, exp_s, exp_n, pi, out);
    reduce_m_kernel<<<dim3(16, 32), 256>>>(out);
}